// round 1
// baseline (speedup 1.0000x reference)
#include <cuda_runtime.h>
#include <cstdint>

// ---------------------------------------------------------------------------
// GraphSAGE with LSTM aggregation, 3 layers.
//   layer l:  neigh = x[src2d]            [N,16,128]  (gather)
//             aggr  = LSTM_last(neigh)    [N,128]     (16 sequential steps)
//             y     = aggr@Wl^T + bl + x@Wr^T  (+ReLU for layers 1,2)
//
// Per LSTM step: G[m,0:512] = concat(x_t[m], h[m]) @ [Wih|Whh]^T + (bih+bhh)
// computed by a tiled fp32 GEMM using packed fma.rn.f32x2 (2 FMA/lane),
// then a pointwise LSTM state update.
// ---------------------------------------------------------------------------

#define NN   50000
#define DEG  16
#define FDIM 128
#define GDIM 512

// scratch (static __device__ arrays: allocation-free per harness rules)
__device__ float g_H [NN * FDIM];   // LSTM hidden state / aggr
__device__ float g_C [NN * FDIM];   // LSTM cell state
__device__ float g_G [NN * GDIM];   // gate pre-activations
__device__ float g_A1[NN * FDIM];   // layer-1 output
__device__ float g_A2[NN * FDIM];   // layer-2 output

// ---- packed f32x2 helpers --------------------------------------------------
__device__ __forceinline__ unsigned long long pack2(float x, float y) {
    unsigned long long r;
    unsigned int xi = __float_as_uint(x), yi = __float_as_uint(y);
    asm("mov.b64 %0, {%1, %2};" : "=l"(r) : "r"(xi), "r"(yi));
    return r;
}
__device__ __forceinline__ unsigned long long fma2(unsigned long long a,
                                                   unsigned long long b,
                                                   unsigned long long c) {
    unsigned long long d;
    asm("fma.rn.f32x2 %0, %1, %2, %3;" : "=l"(d) : "l"(a), "l"(b), "l"(c));
    return d;
}
__device__ __forceinline__ float2 unpack2(unsigned long long v) {
    unsigned int lo, hi;
    asm("mov.b64 {%0, %1}, %2;" : "=r"(lo), "=r"(hi) : "l"(v));
    return make_float2(__uint_as_float(lo), __uint_as_float(hi));
}

// ---------------------------------------------------------------------------
// gates GEMM: G[m, n] = sum_{k<128} X[src[m*16+t]][k] * Wih[n][k]
//                     + sum_{k<128} g_H[m][k]         * Whh[n][k]
//                     + bih[n] + bhh[n]
// Tile: BM=64, BN=128, BK=16; 256 threads; per-thread 4(m) x 8(n) outputs
// held as 4x4 packed f32x2 accumulators.
// ---------------------------------------------------------------------------
__global__ __launch_bounds__(256)
void gates_kernel(const float* __restrict__ X, const int* __restrict__ src, int t,
                  const float* __restrict__ Wih, const float* __restrict__ Whh,
                  const float* __restrict__ bih, const float* __restrict__ bhh)
{
    __shared__ float As[16][72];    // [k][m], padded
    __shared__ float Bs[16][136];   // [k][n], padded

    const int tid = threadIdx.x;
    const int m0 = blockIdx.x * 64;
    const int n0 = blockIdx.y * 128;
    const int tm = tid & 15;        // 16 m-groups
    const int tn = tid >> 4;        // 16 n-groups

    unsigned long long acc[4][4];
#pragma unroll
    for (int i = 0; i < 4; i++)
#pragma unroll
        for (int j = 0; j < 4; j++) acc[i][j] = 0ull;

    // A loader: threads 0..127, each loads 8 consecutive k of one row
    const int mA  = tid >> 1;
    const int kA0 = (tid & 1) * 8;
    const float* arowx = nullptr;
    const float* arowh = nullptr;
    if (tid < 128) {
        int node = m0 + mA;
        if (node < NN) {
            arowx = X + (size_t)src[node * DEG + t] * FDIM;
            arowh = g_H + (size_t)node * FDIM;
        }
    }
    // B loader: all 256 threads, each loads 8 consecutive k of one weight row
    const int nB  = tid >> 1;
    const int kB0 = (tid & 1) * 8;
    const float* browi = Wih + (size_t)(n0 + nB) * FDIM;
    const float* browh = Whh + (size_t)(n0 + nB) * FDIM;

    for (int k0 = 0; k0 < 256; k0 += 16) {
        float4 a0 = make_float4(0.f, 0.f, 0.f, 0.f), a1 = a0;
        if (tid < 128 && arowx) {
            const float* ar = (k0 < 128) ? (arowx + k0) : (arowh + k0 - 128);
            a0 = *(const float4*)(ar + kA0);
            a1 = *(const float4*)(ar + kA0 + 4);
        }
        const float* br = (k0 < 128) ? (browi + k0) : (browh + k0 - 128);
        float4 b0 = *(const float4*)(br + kB0);
        float4 b1 = *(const float4*)(br + kB0 + 4);

        __syncthreads();
        if (tid < 128) {
            As[kA0 + 0][mA] = a0.x; As[kA0 + 1][mA] = a0.y;
            As[kA0 + 2][mA] = a0.z; As[kA0 + 3][mA] = a0.w;
            As[kA0 + 4][mA] = a1.x; As[kA0 + 5][mA] = a1.y;
            As[kA0 + 6][mA] = a1.z; As[kA0 + 7][mA] = a1.w;
        }
        Bs[kB0 + 0][nB] = b0.x; Bs[kB0 + 1][nB] = b0.y;
        Bs[kB0 + 2][nB] = b0.z; Bs[kB0 + 3][nB] = b0.w;
        Bs[kB0 + 4][nB] = b1.x; Bs[kB0 + 5][nB] = b1.y;
        Bs[kB0 + 6][nB] = b1.z; Bs[kB0 + 7][nB] = b1.w;
        __syncthreads();

#pragma unroll
        for (int kk = 0; kk < 16; kk++) {
            float4 av = *(const float4*)(&As[kk][tm * 4]);
            unsigned long long ap[4];
            ap[0] = pack2(av.x, av.x); ap[1] = pack2(av.y, av.y);
            ap[2] = pack2(av.z, av.z); ap[3] = pack2(av.w, av.w);
            const unsigned long long* bp =
                (const unsigned long long*)(&Bs[kk][tn * 8]);
            unsigned long long bq0 = bp[0], bq1 = bp[1], bq2 = bp[2], bq3 = bp[3];
#pragma unroll
            for (int i = 0; i < 4; i++) {
                acc[i][0] = fma2(ap[i], bq0, acc[i][0]);
                acc[i][1] = fma2(ap[i], bq1, acc[i][1]);
                acc[i][2] = fma2(ap[i], bq2, acc[i][2]);
                acc[i][3] = fma2(ap[i], bq3, acc[i][3]);
            }
        }
    }

#pragma unroll
    for (int i = 0; i < 4; i++) {
        int m = m0 + tm * 4 + i;
        if (m >= NN) continue;
        float* gout = g_G + (size_t)m * GDIM + n0 + tn * 8;
#pragma unroll
        for (int j = 0; j < 4; j++) {
            float2 v = unpack2(acc[i][j]);
            int n = n0 + tn * 8 + 2 * j;
            gout[2 * j + 0] = v.x + bih[n + 0] + bhh[n + 0];
            gout[2 * j + 1] = v.y + bih[n + 1] + bhh[n + 1];
        }
    }
}

// ---------------------------------------------------------------------------
// pointwise LSTM state update (gate order i,f,g,o)
// ---------------------------------------------------------------------------
__global__ void lstm_update_kernel()
{
    int idx = blockIdx.x * blockDim.x + threadIdx.x;
    if (idx >= NN * FDIM) return;
    int m = idx >> 7, j = idx & 127;
    const float* g = g_G + (size_t)m * GDIM;
    float gi = g[j], gf = g[j + 128], gg = g[j + 256], go = g[j + 384];
    float si = 1.f / (1.f + expf(-gi));
    float sf = 1.f / (1.f + expf(-gf));
    float so = 1.f / (1.f + expf(-go));
    float c  = sf * g_C[idx] + si * tanhf(gg);
    g_C[idx] = c;
    g_H[idx] = so * tanhf(c);
}

__global__ void zero_hc_kernel()
{
    int idx = blockIdx.x * blockDim.x + threadIdx.x;
    if (idx >= NN * FDIM) return;
    g_H[idx] = 0.f;
    g_C[idx] = 0.f;
}

// ---------------------------------------------------------------------------
// output GEMM: Out[m, n] = aggr[m]@Wl[n] + X[m]@Wr[n] + bl[n]  (opt ReLU)
// aggr = g_H (final LSTM h). BN=128 tile covers Fo<=128 with guards.
// ---------------------------------------------------------------------------
template<bool RELU>
__global__ __launch_bounds__(256)
void out_kernel(const float* __restrict__ X,
                const float* __restrict__ Wl, const float* __restrict__ Wr,
                const float* __restrict__ bl, float* __restrict__ Out, int Fo)
{
    __shared__ float As[16][72];
    __shared__ float Bs[16][136];

    const int tid = threadIdx.x;
    const int m0 = blockIdx.x * 64;
    const int tm = tid & 15;
    const int tn = tid >> 4;

    unsigned long long acc[4][4];
#pragma unroll
    for (int i = 0; i < 4; i++)
#pragma unroll
        for (int j = 0; j < 4; j++) acc[i][j] = 0ull;

    const int mA  = tid >> 1;
    const int kA0 = (tid & 1) * 8;
    const float* arowa = nullptr;   // aggr (g_H)
    const float* arowx = nullptr;   // layer input
    if (tid < 128) {
        int node = m0 + mA;
        if (node < NN) {
            arowa = g_H + (size_t)node * FDIM;
            arowx = X + (size_t)node * FDIM;
        }
    }
    const int nB  = tid >> 1;
    const int kB0 = (tid & 1) * 8;
    const bool nb_ok = (nB < Fo);
    const float* browl = Wl + (size_t)nB * FDIM;
    const float* browr = Wr + (size_t)nB * FDIM;

    for (int k0 = 0; k0 < 256; k0 += 16) {
        float4 a0 = make_float4(0.f, 0.f, 0.f, 0.f), a1 = a0;
        if (tid < 128 && arowa) {
            const float* ar = (k0 < 128) ? (arowa + k0) : (arowx + k0 - 128);
            a0 = *(const float4*)(ar + kA0);
            a1 = *(const float4*)(ar + kA0 + 4);
        }
        float4 b0 = make_float4(0.f, 0.f, 0.f, 0.f), b1 = b0;
        if (nb_ok) {
            const float* br = (k0 < 128) ? (browl + k0) : (browr + k0 - 128);
            b0 = *(const float4*)(br + kB0);
            b1 = *(const float4*)(br + kB0 + 4);
        }

        __syncthreads();
        if (tid < 128) {
            As[kA0 + 0][mA] = a0.x; As[kA0 + 1][mA] = a0.y;
            As[kA0 + 2][mA] = a0.z; As[kA0 + 3][mA] = a0.w;
            As[kA0 + 4][mA] = a1.x; As[kA0 + 5][mA] = a1.y;
            As[kA0 + 6][mA] = a1.z; As[kA0 + 7][mA] = a1.w;
        }
        Bs[kB0 + 0][nB] = b0.x; Bs[kB0 + 1][nB] = b0.y;
        Bs[kB0 + 2][nB] = b0.z; Bs[kB0 + 3][nB] = b0.w;
        Bs[kB0 + 4][nB] = b1.x; Bs[kB0 + 5][nB] = b1.y;
        Bs[kB0 + 6][nB] = b1.z; Bs[kB0 + 7][nB] = b1.w;
        __syncthreads();

#pragma unroll
        for (int kk = 0; kk < 16; kk++) {
            float4 av = *(const float4*)(&As[kk][tm * 4]);
            unsigned long long ap[4];
            ap[0] = pack2(av.x, av.x); ap[1] = pack2(av.y, av.y);
            ap[2] = pack2(av.z, av.z); ap[3] = pack2(av.w, av.w);
            const unsigned long long* bp =
                (const unsigned long long*)(&Bs[kk][tn * 8]);
            unsigned long long bq0 = bp[0], bq1 = bp[1], bq2 = bp[2], bq3 = bp[3];
#pragma unroll
            for (int i = 0; i < 4; i++) {
                acc[i][0] = fma2(ap[i], bq0, acc[i][0]);
                acc[i][1] = fma2(ap[i], bq1, acc[i][1]);
                acc[i][2] = fma2(ap[i], bq2, acc[i][2]);
                acc[i][3] = fma2(ap[i], bq3, acc[i][3]);
            }
        }
    }

#pragma unroll
    for (int i = 0; i < 4; i++) {
        int m = m0 + tm * 4 + i;
        if (m >= NN) continue;
#pragma unroll
        for (int j = 0; j < 4; j++) {
            float2 v = unpack2(acc[i][j]);
            int n = tn * 8 + 2 * j;
            if (n < Fo) {
                float o0 = v.x + bl[n];
                if (RELU) o0 = fmaxf(o0, 0.f);
                Out[(size_t)m * Fo + n] = o0;
            }
            if (n + 1 < Fo) {
                float o1 = v.y + bl[n + 1];
                if (RELU) o1 = fmaxf(o1, 0.f);
                Out[(size_t)m * Fo + n + 1] = o1;
            }
        }
    }
}

// ---------------------------------------------------------------------------
// host launcher
// ---------------------------------------------------------------------------
extern "C" void kernel_launch(void* const* d_in, const int* in_sizes, int n_in,
                              void* d_out, int out_size)
{
    (void)in_sizes; (void)n_in; (void)out_size;
    const float* x   = (const float*)d_in[0];
    const int*   src = (const int*)d_in[1];   // edge_index row 0 = src (E=800000)

    const float* P[21];
    for (int i = 0; i < 21; i++) P[i] = (const float*)d_in[2 + i];
    // per layer: W_ih, W_hh, b_ih, b_hh, Wl, bl, Wr

    float *a1 = nullptr, *a2 = nullptr;
    cudaGetSymbolAddress((void**)&a1, g_A1);
    cudaGetSymbolAddress((void**)&a2, g_A2);

    const dim3 blk(256);
    const dim3 gGates((NN + 63) / 64, 4);
    const dim3 gOut((NN + 63) / 64, 1);
    const int upBlocks = (NN * FDIM + 255) / 256;

    const float* Xin = x;
    for (int l = 0; l < 3; l++) {
        const float* Wih = P[7 * l + 0];
        const float* Whh = P[7 * l + 1];
        const float* bih = P[7 * l + 2];
        const float* bhh = P[7 * l + 3];
        const float* Wl  = P[7 * l + 4];
        const float* bl  = P[7 * l + 5];
        const float* Wr  = P[7 * l + 6];

        zero_hc_kernel<<<upBlocks, blk>>>();
        for (int t = 0; t < DEG; t++) {
            gates_kernel<<<gGates, blk>>>(Xin, src, t, Wih, Whh, bih, bhh);
            lstm_update_kernel<<<upBlocks, blk>>>();
        }
        if (l == 0) {
            out_kernel<true><<<gOut, blk>>>(Xin, Wl, Wr, bl, a1, 128);
            Xin = a1;
        } else if (l == 1) {
            out_kernel<true><<<gOut, blk>>>(Xin, Wl, Wr, bl, a2, 128);
            Xin = a2;
        } else {
            out_kernel<false><<<gOut, blk>>>(Xin, Wl, Wr, bl, (float*)d_out, 64);
        }
    }
}